// round 15
// baseline (speedup 1.0000x reference)
#include <cuda_runtime.h>
#include <cuda_fp16.h>
#include <cstdint>

#define B_ 4
#define C_ 64
#define N_ 4096
#define NT2 32              // 4096 / 128-key tiles
#define LOG2E 1.4426950408889634f
#define ONES16 0x3C003C00u
#define MLAG 12.0f          // lagging-max threshold: p <= 2^12 fits fp16 exactly-relatively

// Fragment-ordered scratch. uint4 units.
__device__ uint4 g_qf[4 * 256 * 2 * 4 * 32];
__device__ uint4 g_kf[4 * 64 * 2 * 4 * 4 * 32];
__device__ uint4 g_vf[4 * 64 * 4 * 4 * 32];

// ---------------------------------------------------------------------------
__device__ __forceinline__ void cp16(uint32_t d, const void* g) {
    asm volatile("cp.async.cg.shared.global [%0], [%1], 16;"
                 :: "r"(d), "l"(__cvta_generic_to_global(g)) : "memory");
}
__device__ __forceinline__ uint4 lds128(uint32_t a) {
    uint4 r;
    asm volatile("ld.shared.v4.u32 {%0,%1,%2,%3}, [%4];"
                 : "=r"(r.x), "=r"(r.y), "=r"(r.z), "=r"(r.w) : "r"(a));
    return r;
}
__device__ __forceinline__ void mma16816(float* d, const uint32_t* a,
                                         uint32_t b0, uint32_t b1) {
    asm volatile("mma.sync.aligned.m16n8k16.row.col.f32.f16.f16.f32 "
        "{%0,%1,%2,%3}, {%4,%5,%6,%7}, {%8,%9}, {%0,%1,%2,%3};"
        : "+f"(d[0]), "+f"(d[1]), "+f"(d[2]), "+f"(d[3])
        : "r"(a[0]), "r"(a[1]), "r"(a[2]), "r"(a[3]), "r"(b0), "r"(b1));
}
__device__ __forceinline__ uint32_t cvtpk(float hi, float lo) {
    uint32_t r;
    asm("cvt.rn.f16x2.f32 %0, %1, %2;" : "=r"(r) : "f"(hi), "f"(lo));
    return r;
}
__device__ __forceinline__ uint32_t ex2x2(uint32_t a) {
    uint32_t r;
    asm("ex2.approx.f16x2 %0, %1;" : "=r"(r) : "r"(a));
    return r;
}
__device__ __forceinline__ float ex2f(float x) {
    float r;
    asm("ex2.approx.f32 %0, %1;" : "=f"(r) : "f"(x));
    return r;
}
__device__ __forceinline__ uint32_t pkh(float x0, float x1) {
    __half h0 = __float2half_rn(x0), h1 = __float2half_rn(x1);
    return ((uint32_t)__half_as_ushort(h1) << 16) | __half_as_ushort(h0);
}

// 128-key tile: K(hi+lo) 32KB + V(hi) 16KB. 128 threads.
__device__ __forceinline__ void copy_tile(uint32_t sdst, int b, int t2, int tid) {
    const uint4* gk = g_kf + ((size_t)b * 64 + t2 * 2) * 1024;
    const uint4* gv = g_vf + ((size_t)b * 64 + t2 * 2) * 512;
    #pragma unroll
    for (int k = 0; k < 16; k++) {
        int i = tid + k * 128;
        cp16(sdst + i * 16, gk + i);
    }
    #pragma unroll
    for (int k = 0; k < 8; k++) {
        int i = tid + k * 128;
        cp16(sdst + 32768 + i * 16, gv + i);
    }
}

// ---------------------------------------------------------------------------
// Flash attention: 64 q-rows/CTA, 128-key tiles. Softmax FUSED into the QK
// MMA stream (jp-group software pipeline + speculative lagging-max), PV
// in-tile, ONE barrier per tile, prefetch overlapping the whole iteration.
// ---------------------------------------------------------------------------
__global__ void __launch_bounds__(128, 2) attn_tc(float* __restrict__ out)
{
    extern __shared__ uint8_t smraw[];
    const uint32_t smbase = (uint32_t)__cvta_generic_to_shared(smraw);
    const int tid = threadIdx.x, w = tid >> 5, lane = tid & 31;
    const int g = lane >> 2, tq = lane & 3;
    const int b = blockIdx.x >> 6, qblk = blockIdx.x & 63;

    // persistent Q fragments (hi/lo), 32 regs
    uint32_t qh[4][4], ql[4][4];
    {
        const uint4* qp = g_qf + ((size_t)(b * 256 + qblk * 4 + w)) * 256 + lane;
        #pragma unroll
        for (int cs = 0; cs < 4; cs++) {
            uint4 h = qp[cs * 32];
            qh[cs][0] = h.x; qh[cs][1] = h.y; qh[cs][2] = h.z; qh[cs][3] = h.w;
            uint4 l = qp[128 + cs * 32];
            ql[cs][0] = l.x; ql[cs][1] = l.y; ql[cs][2] = l.z; ql[cs][3] = l.w;
        }
    }

    float o[9][4];
    #pragma unroll
    for (int nb = 0; nb < 9; nb++)
        #pragma unroll
        for (int i = 0; i < 4; i++) o[nb][i] = 0.f;
    // mu starts at 0: tile 0's max (>12 with prob ~1) triggers the recompute
    // path, which installs the true max. Uniform loop, no special case.
    float mu0 = 0.f, mu1 = 0.f;

    const uint32_t lanoff = (uint32_t)(lane * 16);
    float s[16][4];
    uint32_t p[16][2];

    copy_tile(smbase, b, 0, tid);
    asm volatile("cp.async.commit_group;" ::: "memory");

    // one jp group = 24 MMAs finalizing s[2jp], s[2jp+1]
    auto qk_jp = [&](uint32_t sK, int jp) {
        float* sa = s[2 * jp];
        float* sb = s[2 * jp + 1];
        #pragma unroll
        for (int cs = 0; cs < 4; cs++) {
            uint32_t base = sK + (jp >> 2) * 16384
                          + (cs * 4 + (jp & 3)) * 512 + lanoff;
            uint4 KH = lds128(base);
            uint4 KL = lds128(base + 8192);
            mma16816(sa, qh[cs], KH.x, KH.y);
            mma16816(sb, qh[cs], KH.z, KH.w);
            mma16816(sa, ql[cs], KH.x, KH.y);
            mma16816(sb, ql[cs], KH.z, KH.w);
            mma16816(sa, qh[cs], KL.x, KL.y);
            mma16816(sb, qh[cs], KL.z, KL.w);
        }
    };

    for (int t = 0; t < NT2; t++) {
        asm volatile("cp.async.wait_group 0;" ::: "memory");
        __syncthreads();          // tile t visible; old buffer reads all done
        if (t + 1 < NT2) {        // prefetch overlaps the WHOLE iteration
            copy_tile(smbase + ((t + 1) & 1) * 49152, b, t + 1, tid);
            asm volatile("cp.async.commit_group;" ::: "memory");
        }
        const uint32_t sK = smbase + (t & 1) * 49152;
        const uint32_t sV = sK + 32768;

        // ---- fused QK + speculative softmax, pipelined over jp groups ----
        #pragma unroll
        for (int nb = 0; nb < 16; nb++) {
            s[nb][0] = 0.f; s[nb][1] = 0.f; s[nb][2] = 0.f; s[nb][3] = 0.f;
        }

        qk_jp(sK, 0);
        float t0 = -1e30f, t1 = -1e30f;
        #pragma unroll
        for (int jg = 0; jg < 8; jg++) {
            if (jg < 7) qk_jp(sK, jg + 1);   // next group's MMAs in flight
            float* sa = s[2 * jg];           // this group's ALU hides under them
            float* sb = s[2 * jg + 1];
            t0 = fmaxf(t0, fmaxf(fmaxf(sa[0], sa[1]), fmaxf(sb[0], sb[1])));
            t1 = fmaxf(t1, fmaxf(fmaxf(sa[2], sa[3]), fmaxf(sb[2], sb[3])));
            p[2*jg][0]   = ex2x2(cvtpk(sa[1] - mu0, sa[0] - mu0));
            p[2*jg][1]   = ex2x2(cvtpk(sa[3] - mu1, sa[2] - mu1));
            p[2*jg+1][0] = ex2x2(cvtpk(sb[1] - mu0, sb[0] - mu0));
            p[2*jg+1][1] = ex2x2(cvtpk(sb[3] - mu1, sb[2] - mu1));
        }

        t0 = fmaxf(t0, __shfl_xor_sync(0xffffffffu, t0, 1));
        t0 = fmaxf(t0, __shfl_xor_sync(0xffffffffu, t0, 2));
        t1 = fmaxf(t1, __shfl_xor_sync(0xffffffffu, t1, 1));
        t1 = fmaxf(t1, __shfl_xor_sync(0xffffffffu, t1, 2));

        bool need = (t0 > mu0 + MLAG) || (t1 > mu1 + MLAG);
        if (__ballot_sync(0xffffffffu, need)) {   // rare: move mu, redo p, rescale o
            const float m0n = fmaxf(mu0, t0), m1n = fmaxf(mu1, t1);
            const float ra0 = ex2f(mu0 - m0n), ra1 = ex2f(mu1 - m1n);
            #pragma unroll
            for (int nb = 0; nb < 16; nb++) {
                p[nb][0] = ex2x2(cvtpk(s[nb][1] - m0n, s[nb][0] - m0n));
                p[nb][1] = ex2x2(cvtpk(s[nb][3] - m1n, s[nb][2] - m1n));
            }
            #pragma unroll
            for (int nb = 0; nb < 9; nb++) {
                o[nb][0] *= ra0; o[nb][1] *= ra0;
                o[nb][2] *= ra1; o[nb][3] *= ra1;
            }
            mu0 = m0n; mu1 = m1n;
        }

        // ---- O += P V (+ ones-column rowsum), same tile ----
        #pragma unroll
        for (int s4 = 0; s4 < 8; s4++) {
            uint32_t a[4] = { p[2*s4][0], p[2*s4][1],
                              p[2*s4+1][0], p[2*s4+1][1] };
            #pragma unroll
            for (int cp = 0; cp < 4; cp++) {
                uint4 VH = lds128(sV + (s4 >> 2) * 8192
                                  + ((s4 & 3) * 4 + cp) * 512 + lanoff);
                mma16816(o[2*cp],   a, VH.x, VH.y);
                mma16816(o[2*cp+1], a, VH.z, VH.w);
            }
            mma16816(o[8], a, ONES16, ONES16);
        }
    }
    __syncthreads();

    // --- epilogue: divide by rowsum, stage via smem for coalesced stores ---
    float* sm = (float*)smraw;  // stride-68 staging, conflict-free
    const float i0 = 1.f / o[8][0], i1 = 1.f / o[8][2];
    const int r0 = w * 16 + g;
    #pragma unroll
    for (int nb = 0; nb < 8; nb++) {
        const int c0 = nb * 8 + 2 * tq;
        sm[c0 * 68 + r0]           = o[nb][0] * i0;
        sm[(c0 + 1) * 68 + r0]     = o[nb][1] * i0;
        sm[c0 * 68 + r0 + 8]       = o[nb][2] * i1;
        sm[(c0 + 1) * 68 + r0 + 8] = o[nb][3] * i1;
    }
    __syncthreads();
    #pragma unroll
    for (int k = 0; k < 8; k++) {
        int idx = tid + k * 128;
        int c = idx >> 4, i4 = (idx & 15) << 2;
        *(float4*)&out[((size_t)b * 64 + c) * 4096 + qblk * 64 + i4] =
            *(float4*)&sm[c * 68 + i4];
    }
}

// ---------------------------------------------------------------------------
// Tensor-core QKV (unchanged from R13/R14).
// ---------------------------------------------------------------------------
__global__ void __launch_bounds__(128, 3) qkv_tc(
    const float* __restrict__ x,
    const float* __restrict__ Wq, const float* __restrict__ bq,
    const float* __restrict__ Wk, const float* __restrict__ bk,
    const float* __restrict__ Wv, const float* __restrict__ bv)
{
    __shared__ uint4 WF[2][4][4][32];      // [hl][cs][jp][lane] : W frag tile
    __shared__ uint4 XF[2][2][4][4][32];   // [half][hl][cs][jp][lane] : x tile

    const int tid = threadIdx.x, lane = tid & 31, w = tid >> 5;
    const int g = lane >> 2, tq = lane & 3;
    const int n0 = blockIdx.x * 128, b = blockIdx.y, m = blockIdx.z;

    const float* Wm = (m == 0) ? Wq : (m == 1) ? Wk : Wv;
    const float* bm = (m == 0) ? bq : (m == 1) ? bk : bv;

    // --- convert W (64x64) into frag tile (rows = out-ch, k = in-ch) ---
    {
        uint32_t* wfu = (uint32_t*)WF;
        const int o = tid & 63, cg = tid >> 6;
        const int jp = (o >> 4) & 3, bsel = (o >> 3) & 1;
        #pragma unroll
        for (int f = 0; f < 8; f++) {
            int c4 = (cg * 8 + f) * 4;
            float4 wv = *(const float4*)&Wm[o * 64 + c4];
            #pragma unroll
            for (int h = 0; h < 2; h++) {
                float v0 = h ? wv.z : wv.x, v1 = h ? wv.w : wv.y;
                int kp = (c4 >> 1) + h;
                __half h0 = __float2half_rn(v0), h1 = __float2half_rn(v1);
                uint32_t hi = ((uint32_t)__half_as_ushort(h1) << 16)
                            | __half_as_ushort(h0);
                uint32_t lo = pkh(v0 - __half2float(h0), v1 - __half2float(h1));
                int cs = kp >> 3, ln = (o & 7) * 4 + (kp & 3);
                int idx = bsel * 2 + ((kp >> 2) & 1);
                int off = (cs * 4 + jp) * 128 + ln * 4 + idx;
                wfu[off] = hi;
                wfu[off + 2048] = lo;
            }
        }
    }

    // --- convert x tile (64 ch x 128 tokens) into frag tile (rows = token) ---
    {
        uint32_t* xfu = (uint32_t*)XF;
        const int cp = tid >> 2, tqd = tid & 3;
        const int cs = cp >> 3;
        const float* x0p = x + ((size_t)(b * 64 + 2 * cp)) * 4096 + n0;
        const float* x1p = x0p + 4096;
        #pragma unroll
        for (int t4 = 0; t4 < 8; t4++) {
            int nn = tqd * 32 + t4 * 4;
            float4 v0 = *(const float4*)&x0p[nn];
            float4 v1 = *(const float4*)&x1p[nn];
            #pragma unroll
            for (int e = 0; e < 4; e++) {
                float a0 = (&v0.x)[e], a1 = (&v1.x)[e];
                __half h0 = __float2half_rn(a0), h1 = __float2half_rn(a1);
                uint32_t hi = ((uint32_t)__half_as_ushort(h1) << 16)
                            | __half_as_ushort(h0);
                uint32_t lo = pkh(a0 - __half2float(h0), a1 - __half2float(h1));
                int rr = nn + e, half = rr >> 6, r6 = rr & 63;
                int jp = (r6 >> 4) & 3, bsel = (r6 >> 3) & 1;
                int ln = (r6 & 7) * 4 + (cp & 3);
                int idx = bsel * 2 + ((cp >> 2) & 1);
                int off = half * 4096 + (cs * 4 + jp) * 128 + ln * 4 + idx;
                xfu[off] = hi;
                xfu[off + 2048] = lo;
            }
        }
    }
    __syncthreads();

    if (m < 2) {
        // D = tokens(M) x out-channels(N); warp handles rowblocks 2w, 2w+1
        #pragma unroll 1
        for (int rbi = 0; rbi < 2; rbi++) {
            const int rb = w * 2 + rbi;
            float acc[8][4];
            #pragma unroll
            for (int nb = 0; nb < 8; nb++)
                #pragma unroll
                for (int i = 0; i < 4; i++) acc[nb][i] = 0.f;

            #pragma unroll
            for (int cs = 0; cs < 4; cs++) {
                uint4 Xh = XF[rb >> 2][0][cs][rb & 3][lane];
                uint4 Xl = XF[rb >> 2][1][cs][rb & 3][lane];
                uint32_t ah[4] = { Xh.x, Xh.z, Xh.y, Xh.w };
                uint32_t al[4] = { Xl.x, Xl.z, Xl.y, Xl.w };
                #pragma unroll
                for (int jp = 0; jp < 4; jp++) {
                    uint4 Wh = WF[0][cs][jp][lane];
                    uint4 Wl = WF[1][cs][jp][lane];
                    mma16816(acc[2*jp],   ah, Wh.x, Wh.y);
                    mma16816(acc[2*jp],   al, Wh.x, Wh.y);
                    mma16816(acc[2*jp],   ah, Wl.x, Wl.y);
                    mma16816(acc[2*jp+1], ah, Wh.z, Wh.w);
                    mma16816(acc[2*jp+1], al, Wh.z, Wh.w);
                    mma16816(acc[2*jp+1], ah, Wl.z, Wl.w);
                }
            }

            // bias (+ LOG2E fold for q)
            #pragma unroll
            for (int nb = 0; nb < 8; nb++) {
                float bb0 = __ldg(&bm[nb * 8 + 2 * tq]);
                float bb1 = __ldg(&bm[nb * 8 + 2 * tq + 1]);
                acc[nb][0] += bb0; acc[nb][1] += bb1;
                acc[nb][2] += bb0; acc[nb][3] += bb1;
                if (m == 0) {
                    acc[nb][0] *= LOG2E; acc[nb][1] *= LOG2E;
                    acc[nb][2] *= LOG2E; acc[nb][3] *= LOG2E;
                }
            }

            uint32_t uAh[8], uBh[8], uAl[8], uBl[8];
            #pragma unroll
            for (int nb = 0; nb < 8; nb++) {
                float d0 = acc[nb][0], d1 = acc[nb][1];
                float d2 = acc[nb][2], d3 = acc[nb][3];
                __half h0 = __float2half_rn(d0), h1 = __float2half_rn(d1);
                __half h2 = __float2half_rn(d2), h3 = __float2half_rn(d3);
                uAh[nb] = ((uint32_t)__half_as_ushort(h1) << 16)
                        | __half_as_ushort(h0);
                uBh[nb] = ((uint32_t)__half_as_ushort(h3) << 16)
                        | __half_as_ushort(h2);
                uAl[nb] = pkh(d0 - __half2float(h0), d1 - __half2float(h1));
                uBl[nb] = pkh(d2 - __half2float(h2), d3 - __half2float(h3));
            }

            const int rowblk = (n0 >> 4) + rb;
            if (m == 0) {
                uint4* dst = g_qf + ((size_t)(b * 256 + rowblk)) * 256 + lane;
                #pragma unroll
                for (int cs = 0; cs < 4; cs++) {
                    dst[cs * 32] =
                        make_uint4(uAh[2*cs], uBh[2*cs], uAh[2*cs+1], uBh[2*cs+1]);
                    dst[128 + cs * 32] =
                        make_uint4(uAl[2*cs], uBl[2*cs], uAl[2*cs+1], uBl[2*cs+1]);
                }
            } else {
                const int jblk = rowblk >> 2, jp2 = rowblk & 3;
                uint4* dst = g_kf + ((size_t)(b * 64 + jblk)) * 1024
                           + jp2 * 32 + lane;
                #pragma unroll
                for (int cs = 0; cs < 4; cs++) {
                    dst[cs * 128] =
                        make_uint4(uAh[2*cs], uAh[2*cs+1], uBh[2*cs], uBh[2*cs+1]);
                    dst[512 + cs * 128] =
                        make_uint4(uAl[2*cs], uAl[2*cs+1], uBl[2*cs], uBl[2*cs+1]);
                }
            }
        }
    } else {
        // V: D = out-channels(M) x tokens(N); warp w owns channel block 16w
        float acc[16][4];
        #pragma unroll
        for (int nb = 0; nb < 16; nb++)
            #pragma unroll
            for (int i = 0; i < 4; i++) acc[nb][i] = 0.f;

        #pragma unroll
        for (int cs = 0; cs < 4; cs++) {
            uint4 Ah4 = WF[0][cs][w][lane];
            uint4 Al4 = WF[1][cs][w][lane];
            uint32_t ah[4] = { Ah4.x, Ah4.z, Ah4.y, Ah4.w };
            uint32_t al[4] = { Al4.x, Al4.z, Al4.y, Al4.w };
            #pragma unroll
            for (int jp = 0; jp < 8; jp++) {
                uint4 Xh = XF[jp >> 2][0][cs][jp & 3][lane];
                uint4 Xl = XF[jp >> 2][1][cs][jp & 3][lane];
                mma16816(acc[2*jp],   ah, Xh.x, Xh.y);
                mma16816(acc[2*jp],   al, Xh.x, Xh.y);
                mma16816(acc[2*jp],   ah, Xl.x, Xl.y);
                mma16816(acc[2*jp+1], ah, Xh.z, Xh.w);
                mma16816(acc[2*jp+1], al, Xh.z, Xh.w);
                mma16816(acc[2*jp+1], ah, Xl.z, Xl.w);
            }
        }

        const float bb0 = __ldg(&bm[16 * w + g]);
        const float bb1 = __ldg(&bm[16 * w + g + 8]);
        uint32_t uA[16], uB[16];
        #pragma unroll
        for (int nb = 0; nb < 16; nb++) {
            uA[nb] = pkh(acc[nb][0] + bb0, acc[nb][1] + bb0);
            uB[nb] = pkh(acc[nb][2] + bb1, acc[nb][3] + bb1);
        }
        #pragma unroll
        for (int ks = 0; ks < 8; ks++) {
            const int jblk = (n0 >> 6) + (ks >> 2), ksl = ks & 3;
            g_vf[((size_t)(b * 64 + jblk)) * 512 + ksl * 128 + w * 32 + lane] =
                make_uint4(uA[2*ks], uA[2*ks+1], uB[2*ks], uB[2*ks+1]);
        }
    }
}

// ---------------------------------------------------------------------------
// Inputs (metadata order): x, t(unused), Wq, bq, Wk, bk, Wv, bv
// ---------------------------------------------------------------------------
extern "C" void kernel_launch(void* const* d_in, const int* in_sizes, int n_in,
                              void* d_out, int out_size) {
    const float* x  = (const float*)d_in[0];
    const float* Wq = (const float*)d_in[2];
    const float* bq = (const float*)d_in[3];
    const float* Wk = (const float*)d_in[4];
    const float* bk = (const float*)d_in[5];
    const float* Wv = (const float*)d_in[6];
    const float* bv = (const float*)d_in[7];
    float* out = (float*)d_out;

    cudaFuncSetAttribute(attn_tc, cudaFuncAttributeMaxDynamicSharedMemorySize,
                         98304);
    qkv_tc<<<dim3(32, B_, 3), 128>>>(x, Wq, bq, Wk, bk, Wv, bv);
    attn_tc<<<B_ * 64, 128, 98304>>>(out);
}

// round 16
// speedup vs baseline: 1.0059x; 1.0059x over previous
#include <cuda_runtime.h>
#include <cuda_fp16.h>
#include <cstdint>

#define B_ 4
#define C_ 64
#define N_ 4096
#define NT2 32              // 4096 / 128-key tiles
#define LOG2E 1.4426950408889634f
#define ONES16 0x3C003C00u
#define MLAG 3.5f           // lagging-max rescale threshold (log2 units)

// Fragment-ordered scratch (K/V only now). uint4 units.
__device__ uint4 g_kf[4 * 64 * 2 * 4 * 4 * 32];
__device__ uint4 g_vf[4 * 64 * 4 * 4 * 32];

// ---------------------------------------------------------------------------
__device__ __forceinline__ void cp16(uint32_t d, const void* g) {
    asm volatile("cp.async.cg.shared.global [%0], [%1], 16;"
                 :: "r"(d), "l"(__cvta_generic_to_global(g)) : "memory");
}
__device__ __forceinline__ uint4 lds128(uint32_t a) {
    uint4 r;
    asm volatile("ld.shared.v4.u32 {%0,%1,%2,%3}, [%4];"
                 : "=r"(r.x), "=r"(r.y), "=r"(r.z), "=r"(r.w) : "r"(a));
    return r;
}
__device__ __forceinline__ void mma16816(float* d, const uint32_t* a,
                                         uint32_t b0, uint32_t b1) {
    asm volatile("mma.sync.aligned.m16n8k16.row.col.f32.f16.f16.f32 "
        "{%0,%1,%2,%3}, {%4,%5,%6,%7}, {%8,%9}, {%0,%1,%2,%3};"
        : "+f"(d[0]), "+f"(d[1]), "+f"(d[2]), "+f"(d[3])
        : "r"(a[0]), "r"(a[1]), "r"(a[2]), "r"(a[3]), "r"(b0), "r"(b1));
}
__device__ __forceinline__ uint32_t cvtpk(float hi, float lo) {
    uint32_t r;
    asm("cvt.rn.f16x2.f32 %0, %1, %2;" : "=r"(r) : "f"(hi), "f"(lo));
    return r;
}
__device__ __forceinline__ uint32_t ex2x2(uint32_t a) {
    uint32_t r;
    asm("ex2.approx.f16x2 %0, %1;" : "=r"(r) : "r"(a));
    return r;
}
__device__ __forceinline__ float ex2f(float x) {
    float r;
    asm("ex2.approx.f32 %0, %1;" : "=f"(r) : "f"(x));
    return r;
}
__device__ __forceinline__ uint32_t pkh(float x0, float x1) {
    __half h0 = __float2half_rn(x0), h1 = __float2half_rn(x1);
    return ((uint32_t)__half_as_ushort(h1) << 16) | __half_as_ushort(h0);
}

// 128-key tile: K(hi+lo) 32KB + V(hi) 16KB. 128 threads.
__device__ __forceinline__ void copy_tile(uint32_t sdst, int b, int t2, int tid) {
    const uint4* gk = g_kf + ((size_t)b * 64 + t2 * 2) * 1024;
    const uint4* gv = g_vf + ((size_t)b * 64 + t2 * 2) * 512;
    #pragma unroll
    for (int k = 0; k < 16; k++) {
        int i = tid + k * 128;
        cp16(sdst + i * 16, gk + i);
    }
    #pragma unroll
    for (int k = 0; k < 8; k++) {
        int i = tid + k * 128;
        cp16(sdst + 32768 + i * 16, gv + i);
    }
}

// ---------------------------------------------------------------------------
// Flash attention with FUSED Q-projection prologue (hidden under tile-0 load).
// Main loop = R14: 64 q-rows/CTA, 128-key tiles, deferred-PV + split softmax
// + lagging max.
// ---------------------------------------------------------------------------
__global__ void __launch_bounds__(128, 2) attn_tc(
    float* __restrict__ out,
    const float* __restrict__ x,
    const float* __restrict__ Wq, const float* __restrict__ bq)
{
    extern __shared__ uint8_t smraw[];
    const uint32_t smbase = (uint32_t)__cvta_generic_to_shared(smraw);
    const int tid = threadIdx.x, w = tid >> 5, lane = tid & 31;
    const int g = lane >> 2, tq = lane & 3;
    const int b = blockIdx.x >> 6, qblk = blockIdx.x & 63;

    // start tile-0 K/V load immediately; prologue hides beneath it
    copy_tile(smbase, b, 0, tid);
    asm volatile("cp.async.commit_group;" ::: "memory");

    // ---- Q-projection prologue: q = LOG2E*(Wq x + bq) for this CTA's 64 rows
    // Staging in buffer 1 (smbase+49152): WFQ 16KB hi/lo, XFQ 16KB hi/lo.
    uint32_t qh[4][4], ql[4][4];
    {
        uint32_t* wfu = (uint32_t*)(smraw + 49152);
        uint32_t* xfu = (uint32_t*)(smraw + 49152 + 16384);

        // Wq (64x64) -> frag tile [hl][cs][jp][lane]
        {
            const int o = tid & 63, cg = tid >> 6;
            #pragma unroll
            for (int f = 0; f < 8; f++) {
                int c4 = (cg * 8 + f) * 4;
                float4 wv = *(const float4*)&Wq[o * 64 + c4];
                #pragma unroll
                for (int h = 0; h < 2; h++) {
                    float v0 = h ? wv.z : wv.x, v1 = h ? wv.w : wv.y;
                    int kp = (c4 >> 1) + h;
                    __half h0 = __float2half_rn(v0), h1 = __float2half_rn(v1);
                    uint32_t hi = ((uint32_t)__half_as_ushort(h1) << 16)
                                | __half_as_ushort(h0);
                    uint32_t lo = pkh(v0 - __half2float(h0),
                                      v1 - __half2float(h1));
                    int cs = kp >> 3, ln = (o & 7) * 4 + (kp & 3);
                    int idx = ((o >> 3) & 1) * 2 + ((kp >> 2) & 1);
                    int off = (cs * 4 + ((o >> 4) & 3)) * 128 + ln * 4 + idx;
                    wfu[off] = hi;
                    wfu[off + 2048] = lo;
                }
            }
        }
        // x tile (64 ch x 64 tokens) -> frag tile [hl][cs][jp][lane]
        {
            const int cp = tid >> 2, tqd = tid & 3;
            const int cs = cp >> 3;
            const float* x0p = x + ((size_t)(b * 64 + 2 * cp)) * 4096 + qblk * 64;
            const float* x1p = x0p + 4096;
            #pragma unroll
            for (int t4 = 0; t4 < 4; t4++) {
                int nn = tqd * 16 + t4 * 4;
                float4 v0 = *(const float4*)&x0p[nn];
                float4 v1 = *(const float4*)&x1p[nn];
                #pragma unroll
                for (int e = 0; e < 4; e++) {
                    float a0 = (&v0.x)[e], a1 = (&v1.x)[e];
                    __half h0 = __float2half_rn(a0), h1 = __float2half_rn(a1);
                    uint32_t hi = ((uint32_t)__half_as_ushort(h1) << 16)
                                | __half_as_ushort(h0);
                    uint32_t lo = pkh(a0 - __half2float(h0),
                                      a1 - __half2float(h1));
                    int rr = nn + e;
                    int jp = (rr >> 4) & 3, bsel = (rr >> 3) & 1;
                    int ln = (rr & 7) * 4 + (cp & 3);
                    int idx = bsel * 2 + ((cp >> 2) & 1);
                    int off = (cs * 4 + jp) * 128 + ln * 4 + idx;
                    xfu[off] = hi;
                    xfu[off + 2048] = lo;
                }
            }
        }
        __syncthreads();

        // warp w computes its own rowblock: D = x(16 rows) x Wq^T, 3 products
        float acc[8][4];
        #pragma unroll
        for (int nb = 0; nb < 8; nb++)
            #pragma unroll
            for (int i = 0; i < 4; i++) acc[nb][i] = 0.f;

        const uint4* XFQ = (const uint4*)xfu;
        const uint4* WFQ = (const uint4*)wfu;
        #pragma unroll
        for (int cs = 0; cs < 4; cs++) {
            uint4 Xh = XFQ[(cs * 4 + w) * 32 + lane];
            uint4 Xl = XFQ[512 + (cs * 4 + w) * 32 + lane];
            uint32_t ah[4] = { Xh.x, Xh.z, Xh.y, Xh.w };
            uint32_t al[4] = { Xl.x, Xl.z, Xl.y, Xl.w };
            #pragma unroll
            for (int jp = 0; jp < 4; jp++) {
                uint4 Wh = WFQ[(cs * 4 + jp) * 32 + lane];
                uint4 Wl = WFQ[512 + (cs * 4 + jp) * 32 + lane];
                mma16816(acc[2*jp],   ah, Wh.x, Wh.y);
                mma16816(acc[2*jp],   al, Wh.x, Wh.y);
                mma16816(acc[2*jp],   ah, Wl.x, Wl.y);
                mma16816(acc[2*jp+1], ah, Wh.z, Wh.w);
                mma16816(acc[2*jp+1], al, Wh.z, Wh.w);
                mma16816(acc[2*jp+1], ah, Wl.z, Wl.w);
            }
        }
        #pragma unroll
        for (int nb = 0; nb < 8; nb++) {
            float bb0 = __ldg(&bq[nb * 8 + 2 * tq]);
            float bb1 = __ldg(&bq[nb * 8 + 2 * tq + 1]);
            acc[nb][0] = (acc[nb][0] + bb0) * LOG2E;
            acc[nb][1] = (acc[nb][1] + bb1) * LOG2E;
            acc[nb][2] = (acc[nb][2] + bb0) * LOG2E;
            acc[nb][3] = (acc[nb][3] + bb1) * LOG2E;
        }
        // split to hi/lo A-fragments (layout identical to old g_qf)
        #pragma unroll
        for (int cs = 0; cs < 4; cs++) {
            #pragma unroll
            for (int half = 0; half < 2; half++) {
                int nb = 2 * cs + half;
                float d0 = acc[nb][0], d1 = acc[nb][1];
                float d2 = acc[nb][2], d3 = acc[nb][3];
                __half h0 = __float2half_rn(d0), h1 = __float2half_rn(d1);
                __half h2 = __float2half_rn(d2), h3 = __float2half_rn(d3);
                qh[cs][0 + half * 2] = ((uint32_t)__half_as_ushort(h1) << 16)
                                     | __half_as_ushort(h0);
                qh[cs][1 + half * 2] = ((uint32_t)__half_as_ushort(h3) << 16)
                                     | __half_as_ushort(h2);
                ql[cs][0 + half * 2] = pkh(d0 - __half2float(h0),
                                           d1 - __half2float(h1));
                ql[cs][1 + half * 2] = pkh(d2 - __half2float(h2),
                                           d3 - __half2float(h3));
            }
        }
    }

    float o[9][4];
    #pragma unroll
    for (int nb = 0; nb < 9; nb++)
        #pragma unroll
        for (int i = 0; i < 4; i++) o[nb][i] = 0.f;
    float mu0 = -1e30f, mu1 = -1e30f;
    uint32_t p[16][2];
    float ra0 = 1.f, ra1 = 1.f;
    int pend = 0;

    const uint32_t lanoff = (uint32_t)(lane * 16);
    float s[16][4];

    asm volatile("cp.async.wait_group 0;" ::: "memory");
    __syncthreads();   // tile 0 ready AND prologue staging reads done
    copy_tile(smbase + 49152, b, 1, tid);
    asm volatile("cp.async.commit_group;" ::: "memory");

    // QK with jp-pair interleave (R14)
    auto qk_tile = [&](uint32_t sK) {
        #pragma unroll
        for (int nb = 0; nb < 16; nb++)
            #pragma unroll
            for (int i = 0; i < 4; i++) s[nb][i] = 0.f;
        #pragma unroll
        for (int cs = 0; cs < 4; cs++) {
            #pragma unroll
            for (int jg = 0; jg < 4; jg++) {
                const int jp0 = 2 * jg, jp1 = 2 * jg + 1;
                uint32_t b0 = sK + (jp0 >> 2) * 16384
                            + (cs * 4 + (jp0 & 3)) * 512 + lanoff;
                uint32_t b1 = sK + (jp1 >> 2) * 16384
                            + (cs * 4 + (jp1 & 3)) * 512 + lanoff;
                uint4 KH0 = lds128(b0);
                uint4 KL0 = lds128(b0 + 8192);
                uint4 KH1 = lds128(b1);
                uint4 KL1 = lds128(b1 + 8192);
                float* s0 = s[2*jp0];     float* s1 = s[2*jp0+1];
                float* s2 = s[2*jp1];     float* s3 = s[2*jp1+1];
                mma16816(s0, qh[cs], KH0.x, KH0.y);
                mma16816(s1, qh[cs], KH0.z, KH0.w);
                mma16816(s2, qh[cs], KH1.x, KH1.y);
                mma16816(s3, qh[cs], KH1.z, KH1.w);
                mma16816(s0, ql[cs], KH0.x, KH0.y);
                mma16816(s1, ql[cs], KH0.z, KH0.w);
                mma16816(s2, ql[cs], KH1.x, KH1.y);
                mma16816(s3, ql[cs], KH1.z, KH1.w);
                mma16816(s0, qh[cs], KL0.x, KL0.y);
                mma16816(s1, qh[cs], KL0.z, KL0.w);
                mma16816(s2, qh[cs], KL1.x, KL1.y);
                mma16816(s3, qh[cs], KL1.z, KL1.w);
            }
        }
    };

    auto phase1 = [&]() {
        float t0 = fmaxf(fmaxf(s[0][0], s[0][1]), fmaxf(s[1][0], s[1][1]));
        float t1 = fmaxf(fmaxf(s[0][2], s[0][3]), fmaxf(s[1][2], s[1][3]));
        #pragma unroll
        for (int nb = 2; nb < 16; nb += 2) {
            t0 = fmaxf(t0, fmaxf(fmaxf(s[nb][0], s[nb][1]),
                                 fmaxf(s[nb+1][0], s[nb+1][1])));
            t1 = fmaxf(t1, fmaxf(fmaxf(s[nb][2], s[nb][3]),
                                 fmaxf(s[nb+1][2], s[nb+1][3])));
        }
        t0 = fmaxf(t0, __shfl_xor_sync(0xffffffffu, t0, 1));
        t0 = fmaxf(t0, __shfl_xor_sync(0xffffffffu, t0, 2));
        t1 = fmaxf(t1, __shfl_xor_sync(0xffffffffu, t1, 1));
        t1 = fmaxf(t1, __shfl_xor_sync(0xffffffffu, t1, 2));
        bool need = (t0 > mu0 + MLAG) || (t1 > mu1 + MLAG);
        if (__ballot_sync(0xffffffffu, need)) {
            const float m0n = fmaxf(mu0, t0), m1n = fmaxf(mu1, t1);
            ra0 = ex2f(mu0 - m0n); ra1 = ex2f(mu1 - m1n);
            mu0 = m0n; mu1 = m1n; pend = 1;
        }
        #pragma unroll
        for (int nb = 0; nb < 16; nb++) {
            p[nb][0] = cvtpk(s[nb][1] - mu0, s[nb][0] - mu0);
            p[nb][1] = cvtpk(s[nb][3] - mu1, s[nb][2] - mu1);
        }
    };

    auto phase2_pv = [&](uint32_t sVp) {
        #pragma unroll
        for (int nb = 0; nb < 16; nb++) {
            p[nb][0] = ex2x2(p[nb][0]);
            p[nb][1] = ex2x2(p[nb][1]);
        }
        if (pend) {
            #pragma unroll
            for (int nb = 0; nb < 9; nb++) {
                o[nb][0] *= ra0; o[nb][1] *= ra0;
                o[nb][2] *= ra1; o[nb][3] *= ra1;
            }
            pend = 0;
        }
        #pragma unroll
        for (int s4 = 0; s4 < 8; s4++) {
            uint32_t a[4] = { p[2*s4][0], p[2*s4][1],
                              p[2*s4+1][0], p[2*s4+1][1] };
            #pragma unroll
            for (int cp = 0; cp < 4; cp++) {
                uint4 VH = lds128(sVp + (s4 >> 2) * 8192
                                  + ((s4 & 3) * 4 + cp) * 512 + lanoff);
                mma16816(o[2*cp],   a, VH.x, VH.y);
                mma16816(o[2*cp+1], a, VH.z, VH.w);
            }
            mma16816(o[8], a, ONES16, ONES16);
        }
    };

    // ---- tile 0: QK + phase1 only ----
    qk_tile(smbase);
    phase1();

    // ---- main loop (R14) ----
    for (int t = 1; t < NT2; t++) {
        asm volatile("cp.async.wait_group 0;" ::: "memory");
        __syncthreads();
        const uint32_t sK  = smbase + (t & 1) * 49152;
        const uint32_t sVp = smbase + ((t + 1) & 1) * 49152 + 32768;

        qk_tile(sK);
        phase2_pv(sVp);

        __syncthreads();
        if (t + 1 < NT2) {
            copy_tile(smbase + ((t + 1) & 1) * 49152, b, t + 1, tid);
            asm volatile("cp.async.commit_group;" ::: "memory");
        }
        phase1();
    }

    // ---- tail: PV(NT2-1) ----
    phase2_pv(smbase + ((NT2 - 1) & 1) * 49152 + 32768);
    __syncthreads();

    // --- epilogue ---
    float* sm = (float*)smraw;
    const float i0 = 1.f / o[8][0], i1 = 1.f / o[8][2];
    const int r0 = w * 16 + g;
    #pragma unroll
    for (int nb = 0; nb < 8; nb++) {
        const int c0 = nb * 8 + 2 * tq;
        sm[c0 * 68 + r0]           = o[nb][0] * i0;
        sm[(c0 + 1) * 68 + r0]     = o[nb][1] * i0;
        sm[c0 * 68 + r0 + 8]       = o[nb][2] * i1;
        sm[(c0 + 1) * 68 + r0 + 8] = o[nb][3] * i1;
    }
    __syncthreads();
    #pragma unroll
    for (int k = 0; k < 8; k++) {
        int idx = tid + k * 128;
        int c = idx >> 4, i4 = (idx & 15) << 2;
        *(float4*)&out[((size_t)b * 64 + c) * 4096 + qblk * 64 + i4] =
            *(float4*)&sm[c * 68 + i4];
    }
}

// ---------------------------------------------------------------------------
// Tensor-core K/V projection (Q fused into attn). blockIdx.z: 0=K, 1=V.
// ---------------------------------------------------------------------------
__global__ void __launch_bounds__(128, 3) kv_tc(
    const float* __restrict__ x,
    const float* __restrict__ Wk, const float* __restrict__ bk,
    const float* __restrict__ Wv, const float* __restrict__ bv)
{
    __shared__ uint4 WF[2][4][4][32];
    __shared__ uint4 XF[2][2][4][4][32];

    const int tid = threadIdx.x, lane = tid & 31, w = tid >> 5;
    const int g = lane >> 2;
    const int n0 = blockIdx.x * 128, b = blockIdx.y, m = blockIdx.z;

    const float* Wm = (m == 0) ? Wk : Wv;
    const float* bm = (m == 0) ? bk : bv;

    {
        uint32_t* wfu = (uint32_t*)WF;
        const int o = tid & 63, cg = tid >> 6;
        const int jp = (o >> 4) & 3, bsel = (o >> 3) & 1;
        #pragma unroll
        for (int f = 0; f < 8; f++) {
            int c4 = (cg * 8 + f) * 4;
            float4 wv = *(const float4*)&Wm[o * 64 + c4];
            #pragma unroll
            for (int h = 0; h < 2; h++) {
                float v0 = h ? wv.z : wv.x, v1 = h ? wv.w : wv.y;
                int kp = (c4 >> 1) + h;
                __half h0 = __float2half_rn(v0), h1 = __float2half_rn(v1);
                uint32_t hi = ((uint32_t)__half_as_ushort(h1) << 16)
                            | __half_as_ushort(h0);
                uint32_t lo = pkh(v0 - __half2float(h0), v1 - __half2float(h1));
                int cs = kp >> 3, ln = (o & 7) * 4 + (kp & 3);
                int idx = bsel * 2 + ((kp >> 2) & 1);
                int off = (cs * 4 + jp) * 128 + ln * 4 + idx;
                wfu[off] = hi;
                wfu[off + 2048] = lo;
            }
        }
    }
    {
        uint32_t* xfu = (uint32_t*)XF;
        const int cp = tid >> 2, tqd = tid & 3;
        const int cs = cp >> 3;
        const float* x0p = x + ((size_t)(b * 64 + 2 * cp)) * 4096 + n0;
        const float* x1p = x0p + 4096;
        #pragma unroll
        for (int t4 = 0; t4 < 8; t4++) {
            int nn = tqd * 32 + t4 * 4;
            float4 v0 = *(const float4*)&x0p[nn];
            float4 v1 = *(const float4*)&x1p[nn];
            #pragma unroll
            for (int e = 0; e < 4; e++) {
                float a0 = (&v0.x)[e], a1 = (&v1.x)[e];
                __half h0 = __float2half_rn(a0), h1 = __float2half_rn(a1);
                uint32_t hi = ((uint32_t)__half_as_ushort(h1) << 16)
                            | __half_as_ushort(h0);
                uint32_t lo = pkh(a0 - __half2float(h0), a1 - __half2float(h1));
                int rr = nn + e, half = rr >> 6, r6 = rr & 63;
                int jp = (r6 >> 4) & 3, bsel = (r6 >> 3) & 1;
                int ln = (r6 & 7) * 4 + (cp & 3);
                int idx = bsel * 2 + ((cp >> 2) & 1);
                int off = half * 4096 + (cs * 4 + jp) * 128 + ln * 4 + idx;
                xfu[off] = hi;
                xfu[off + 2048] = lo;
            }
        }
    }
    __syncthreads();

    if (m == 0) {
        // K: D = tokens(M) x out-channels(N); warp handles rowblocks 2w, 2w+1
        const int tq = lane & 3;
        #pragma unroll 1
        for (int rbi = 0; rbi < 2; rbi++) {
            const int rb = w * 2 + rbi;
            float acc[8][4];
            #pragma unroll
            for (int nb = 0; nb < 8; nb++)
                #pragma unroll
                for (int i = 0; i < 4; i++) acc[nb][i] = 0.f;

            #pragma unroll
            for (int cs = 0; cs < 4; cs++) {
                uint4 Xh = XF[rb >> 2][0][cs][rb & 3][lane];
                uint4 Xl = XF[rb >> 2][1][cs][rb & 3][lane];
                uint32_t ah[4] = { Xh.x, Xh.z, Xh.y, Xh.w };
                uint32_t al[4] = { Xl.x, Xl.z, Xl.y, Xl.w };
                #pragma unroll
                for (int jp = 0; jp < 4; jp++) {
                    uint4 Wh = WF[0][cs][jp][lane];
                    uint4 Wl = WF[1][cs][jp][lane];
                    mma16816(acc[2*jp],   ah, Wh.x, Wh.y);
                    mma16816(acc[2*jp],   al, Wh.x, Wh.y);
                    mma16816(acc[2*jp],   ah, Wl.x, Wl.y);
                    mma16816(acc[2*jp+1], ah, Wh.z, Wh.w);
                    mma16816(acc[2*jp+1], al, Wh.z, Wh.w);
                    mma16816(acc[2*jp+1], ah, Wl.z, Wl.w);
                }
            }
            #pragma unroll
            for (int nb = 0; nb < 8; nb++) {
                float bb0 = __ldg(&bm[nb * 8 + 2 * tq]);
                float bb1 = __ldg(&bm[nb * 8 + 2 * tq + 1]);
                acc[nb][0] += bb0; acc[nb][1] += bb1;
                acc[nb][2] += bb0; acc[nb][3] += bb1;
            }
            uint32_t uAh[8], uBh[8], uAl[8], uBl[8];
            #pragma unroll
            for (int nb = 0; nb < 8; nb++) {
                float d0 = acc[nb][0], d1 = acc[nb][1];
                float d2 = acc[nb][2], d3 = acc[nb][3];
                __half h0 = __float2half_rn(d0), h1 = __float2half_rn(d1);
                __half h2 = __float2half_rn(d2), h3 = __float2half_rn(d3);
                uAh[nb] = ((uint32_t)__half_as_ushort(h1) << 16)
                        | __half_as_ushort(h0);
                uBh[nb] = ((uint32_t)__half_as_ushort(h3) << 16)
                        | __half_as_ushort(h2);
                uAl[nb] = pkh(d0 - __half2float(h0), d1 - __half2float(h1));
                uBl[nb] = pkh(d2 - __half2float(h2), d3 - __half2float(h3));
            }
            const int rowblk = (n0 >> 4) + rb;
            const int jblk = rowblk >> 2, jp2 = rowblk & 3;
            uint4* dst = g_kf + ((size_t)(b * 64 + jblk)) * 1024
                       + jp2 * 32 + lane;
            #pragma unroll
            for (int cs = 0; cs < 4; cs++) {
                dst[cs * 128] =
                    make_uint4(uAh[2*cs], uAh[2*cs+1], uBh[2*cs], uBh[2*cs+1]);
                dst[512 + cs * 128] =
                    make_uint4(uAl[2*cs], uAl[2*cs+1], uBl[2*cs], uBl[2*cs+1]);
            }
        }
    } else {
        // V: D = out-channels(M) x tokens(N)
        float acc[16][4];
        #pragma unroll
        for (int nb = 0; nb < 16; nb++)
            #pragma unroll
            for (int i = 0; i < 4; i++) acc[nb][i] = 0.f;

        #pragma unroll
        for (int cs = 0; cs < 4; cs++) {
            uint4 Ah4 = WF[0][cs][w][lane];
            uint4 Al4 = WF[1][cs][w][lane];
            uint32_t ah[4] = { Ah4.x, Ah4.z, Ah4.y, Ah4.w };
            uint32_t al[4] = { Al4.x, Al4.z, Al4.y, Al4.w };
            #pragma unroll
            for (int jp = 0; jp < 8; jp++) {
                uint4 Xh = XF[jp >> 2][0][cs][jp & 3][lane];
                uint4 Xl = XF[jp >> 2][1][cs][jp & 3][lane];
                mma16816(acc[2*jp],   ah, Xh.x, Xh.y);
                mma16816(acc[2*jp],   al, Xh.x, Xh.y);
                mma16816(acc[2*jp],   ah, Xl.x, Xl.y);
                mma16816(acc[2*jp+1], ah, Xh.z, Xh.w);
                mma16816(acc[2*jp+1], al, Xh.z, Xh.w);
                mma16816(acc[2*jp+1], ah, Xl.z, Xl.w);
            }
        }
        const float bb0 = __ldg(&bm[16 * w + g]);
        const float bb1 = __ldg(&bm[16 * w + g + 8]);
        uint32_t uA[16], uB[16];
        #pragma unroll
        for (int nb = 0; nb < 16; nb++) {
            uA[nb] = pkh(acc[nb][0] + bb0, acc[nb][1] + bb0);
            uB[nb] = pkh(acc[nb][2] + bb1, acc[nb][3] + bb1);
        }
        #pragma unroll
        for (int ks = 0; ks < 8; ks++) {
            const int jblk = (n0 >> 6) + (ks >> 2), ksl = ks & 3;
            g_vf[((size_t)(b * 64 + jblk)) * 512 + ksl * 128 + w * 32 + lane] =
                make_uint4(uA[2*ks], uA[2*ks+1], uB[2*ks], uB[2*ks+1]);
        }
    }
}

// ---------------------------------------------------------------------------
// Inputs (metadata order): x, t(unused), Wq, bq, Wk, bk, Wv, bv
// ---------------------------------------------------------------------------
extern "C" void kernel_launch(void* const* d_in, const int* in_sizes, int n_in,
                              void* d_out, int out_size) {
    const float* x  = (const float*)d_in[0];
    const float* Wq = (const float*)d_in[2];
    const float* bq = (const float*)d_in[3];
    const float* Wk = (const float*)d_in[4];
    const float* bk = (const float*)d_in[5];
    const float* Wv = (const float*)d_in[6];
    const float* bv = (const float*)d_in[7];
    float* out = (float*)d_out;

    cudaFuncSetAttribute(attn_tc, cudaFuncAttributeMaxDynamicSharedMemorySize,
                         98304);
    kv_tc<<<dim3(32, B_, 2), 128>>>(x, Wk, bk, Wv, bv);
    attn_tc<<<B_ * 64, 128, 98304>>>(out, x, Wq, bq);
}

// round 17
// speedup vs baseline: 1.0622x; 1.0560x over previous
#include <cuda_runtime.h>
#include <cuda_fp16.h>
#include <cstdint>

#define B_ 4
#define C_ 64
#define N_ 4096
#define NT2 32              // 4096 / 128-key tiles
#define LOG2E 1.4426950408889634f
#define ONES16 0x3C003C00u
#define MLAG 3.5f           // lagging-max rescale threshold (log2 units)

// Fragment-ordered scratch. uint4 units.
__device__ uint4 g_qf[4 * 256 * 2 * 4 * 32];
__device__ uint4 g_kf[4 * 64 * 2 * 4 * 4 * 32];
__device__ uint4 g_vf[4 * 64 * 4 * 4 * 32];

// ---------------------------------------------------------------------------
__device__ __forceinline__ void cp16(uint32_t d, const void* g) {
    asm volatile("cp.async.cg.shared.global [%0], [%1], 16;"
                 :: "r"(d), "l"(__cvta_generic_to_global(g)) : "memory");
}
__device__ __forceinline__ uint4 lds128(uint32_t a) {
    uint4 r;
    asm volatile("ld.shared.v4.u32 {%0,%1,%2,%3}, [%4];"
                 : "=r"(r.x), "=r"(r.y), "=r"(r.z), "=r"(r.w) : "r"(a));
    return r;
}
__device__ __forceinline__ void mma16816(float* d, const uint32_t* a,
                                         uint32_t b0, uint32_t b1) {
    asm volatile("mma.sync.aligned.m16n8k16.row.col.f32.f16.f16.f32 "
        "{%0,%1,%2,%3}, {%4,%5,%6,%7}, {%8,%9}, {%0,%1,%2,%3};"
        : "+f"(d[0]), "+f"(d[1]), "+f"(d[2]), "+f"(d[3])
        : "r"(a[0]), "r"(a[1]), "r"(a[2]), "r"(a[3]), "r"(b0), "r"(b1));
}
__device__ __forceinline__ uint32_t cvtpk(float hi, float lo) {  // pack {hi,lo}
    uint32_t r;
    asm("cvt.rn.f16x2.f32 %0, %1, %2;" : "=r"(r) : "f"(hi), "f"(lo));
    return r;
}
__device__ __forceinline__ uint32_t ex2x2(uint32_t a) {
    uint32_t r;
    asm("ex2.approx.f16x2 %0, %1;" : "=r"(r) : "r"(a));
    return r;
}
__device__ __forceinline__ float ex2f(float x) {
    float r;
    asm("ex2.approx.f32 %0, %1;" : "=f"(r) : "f"(x));
    return r;
}
__device__ __forceinline__ uint32_t pkh(float x0, float x1) {  // {x1,x0}
    return cvtpk(x1, x0);
}
// fast hi/lo fp16 split of a float pair (lo lane = a0)
__device__ __forceinline__ void split2(float a0, float a1,
                                       uint32_t& hi, uint32_t& lo) {
    hi = cvtpk(a1, a0);
    __half2 hh = *(__half2*)&hi;
    float2 f = __half22float2(hh);
    lo = cvtpk(a1 - f.y, a0 - f.x);
}

// 128-key tile: K(hi+lo) 32KB + V(hi) 16KB. 128 threads.
__device__ __forceinline__ void copy_tile(uint32_t sdst, int b, int t2, int tid) {
    const uint4* gk = g_kf + ((size_t)b * 64 + t2 * 2) * 1024;
    const uint4* gv = g_vf + ((size_t)b * 64 + t2 * 2) * 512;
    #pragma unroll
    for (int k = 0; k < 16; k++) {
        int i = tid + k * 128;
        cp16(sdst + i * 16, gk + i);
    }
    #pragma unroll
    for (int k = 0; k < 8; k++) {
        int i = tid + k * 128;
        cp16(sdst + 32768 + i * 16, gv + i);
    }
}

// ---------------------------------------------------------------------------
// Flash attention (R14, unchanged): 64 q-rows/CTA, 128-key tiles,
// deferred-PV + split softmax + lagging max, jp-pair MMA interleave.
// ---------------------------------------------------------------------------
__global__ void __launch_bounds__(128, 2) attn_tc(float* __restrict__ out)
{
    extern __shared__ uint8_t smraw[];
    const uint32_t smbase = (uint32_t)__cvta_generic_to_shared(smraw);
    const int tid = threadIdx.x, w = tid >> 5, lane = tid & 31;
    const int g = lane >> 2, tq = lane & 3;
    const int b = blockIdx.x >> 6, qblk = blockIdx.x & 63;

    // persistent Q fragments (hi/lo), 32 regs
    uint32_t qh[4][4], ql[4][4];
    {
        const uint4* qp = g_qf + ((size_t)(b * 256 + qblk * 4 + w)) * 256 + lane;
        #pragma unroll
        for (int cs = 0; cs < 4; cs++) {
            uint4 h = qp[cs * 32];
            qh[cs][0] = h.x; qh[cs][1] = h.y; qh[cs][2] = h.z; qh[cs][3] = h.w;
            uint4 l = qp[128 + cs * 32];
            ql[cs][0] = l.x; ql[cs][1] = l.y; ql[cs][2] = l.z; ql[cs][3] = l.w;
        }
    }

    float o[9][4];
    #pragma unroll
    for (int nb = 0; nb < 9; nb++)
        #pragma unroll
        for (int i = 0; i < 4; i++) o[nb][i] = 0.f;
    float mu0 = -1e30f, mu1 = -1e30f;
    uint32_t p[16][2];
    float ra0 = 1.f, ra1 = 1.f;
    int pend = 0;

    const uint32_t lanoff = (uint32_t)(lane * 16);
    float s[16][4];

    copy_tile(smbase, b, 0, tid);
    asm volatile("cp.async.commit_group;" ::: "memory");
    asm volatile("cp.async.wait_group 0;" ::: "memory");
    __syncthreads();
    copy_tile(smbase + 49152, b, 1, tid);
    asm volatile("cp.async.commit_group;" ::: "memory");

    auto qk_tile = [&](uint32_t sK) {
        #pragma unroll
        for (int nb = 0; nb < 16; nb++)
            #pragma unroll
            for (int i = 0; i < 4; i++) s[nb][i] = 0.f;
        #pragma unroll
        for (int cs = 0; cs < 4; cs++) {
            #pragma unroll
            for (int jg = 0; jg < 4; jg++) {
                const int jp0 = 2 * jg, jp1 = 2 * jg + 1;
                uint32_t b0 = sK + (jp0 >> 2) * 16384
                            + (cs * 4 + (jp0 & 3)) * 512 + lanoff;
                uint32_t b1 = sK + (jp1 >> 2) * 16384
                            + (cs * 4 + (jp1 & 3)) * 512 + lanoff;
                uint4 KH0 = lds128(b0);
                uint4 KL0 = lds128(b0 + 8192);
                uint4 KH1 = lds128(b1);
                uint4 KL1 = lds128(b1 + 8192);
                float* s0 = s[2*jp0];     float* s1 = s[2*jp0+1];
                float* s2 = s[2*jp1];     float* s3 = s[2*jp1+1];
                mma16816(s0, qh[cs], KH0.x, KH0.y);
                mma16816(s1, qh[cs], KH0.z, KH0.w);
                mma16816(s2, qh[cs], KH1.x, KH1.y);
                mma16816(s3, qh[cs], KH1.z, KH1.w);
                mma16816(s0, ql[cs], KH0.x, KH0.y);
                mma16816(s1, ql[cs], KH0.z, KH0.w);
                mma16816(s2, ql[cs], KH1.x, KH1.y);
                mma16816(s3, ql[cs], KH1.z, KH1.w);
                mma16816(s0, qh[cs], KL0.x, KL0.y);
                mma16816(s1, qh[cs], KL0.z, KL0.w);
                mma16816(s2, qh[cs], KL1.x, KL1.y);
                mma16816(s3, qh[cs], KL1.z, KL1.w);
            }
        }
    };

    auto phase1 = [&]() {
        float t0 = fmaxf(fmaxf(s[0][0], s[0][1]), fmaxf(s[1][0], s[1][1]));
        float t1 = fmaxf(fmaxf(s[0][2], s[0][3]), fmaxf(s[1][2], s[1][3]));
        #pragma unroll
        for (int nb = 2; nb < 16; nb += 2) {
            t0 = fmaxf(t0, fmaxf(fmaxf(s[nb][0], s[nb][1]),
                                 fmaxf(s[nb+1][0], s[nb+1][1])));
            t1 = fmaxf(t1, fmaxf(fmaxf(s[nb][2], s[nb][3]),
                                 fmaxf(s[nb+1][2], s[nb+1][3])));
        }
        t0 = fmaxf(t0, __shfl_xor_sync(0xffffffffu, t0, 1));
        t0 = fmaxf(t0, __shfl_xor_sync(0xffffffffu, t0, 2));
        t1 = fmaxf(t1, __shfl_xor_sync(0xffffffffu, t1, 1));
        t1 = fmaxf(t1, __shfl_xor_sync(0xffffffffu, t1, 2));
        bool need = (t0 > mu0 + MLAG) || (t1 > mu1 + MLAG);
        if (__ballot_sync(0xffffffffu, need)) {
            const float m0n = fmaxf(mu0, t0), m1n = fmaxf(mu1, t1);
            ra0 = ex2f(mu0 - m0n); ra1 = ex2f(mu1 - m1n);
            mu0 = m0n; mu1 = m1n; pend = 1;
        }
        #pragma unroll
        for (int nb = 0; nb < 16; nb++) {
            p[nb][0] = cvtpk(s[nb][1] - mu0, s[nb][0] - mu0);
            p[nb][1] = cvtpk(s[nb][3] - mu1, s[nb][2] - mu1);
        }
    };

    auto phase2_pv = [&](uint32_t sVp) {
        #pragma unroll
        for (int nb = 0; nb < 16; nb++) {
            p[nb][0] = ex2x2(p[nb][0]);
            p[nb][1] = ex2x2(p[nb][1]);
        }
        if (pend) {
            #pragma unroll
            for (int nb = 0; nb < 9; nb++) {
                o[nb][0] *= ra0; o[nb][1] *= ra0;
                o[nb][2] *= ra1; o[nb][3] *= ra1;
            }
            pend = 0;
        }
        #pragma unroll
        for (int s4 = 0; s4 < 8; s4++) {
            uint32_t a[4] = { p[2*s4][0], p[2*s4][1],
                              p[2*s4+1][0], p[2*s4+1][1] };
            #pragma unroll
            for (int cp = 0; cp < 4; cp++) {
                uint4 VH = lds128(sVp + (s4 >> 2) * 8192
                                  + ((s4 & 3) * 4 + cp) * 512 + lanoff);
                mma16816(o[2*cp],   a, VH.x, VH.y);
                mma16816(o[2*cp+1], a, VH.z, VH.w);
            }
            mma16816(o[8], a, ONES16, ONES16);
        }
    };

    qk_tile(smbase);
    phase1();

    for (int t = 1; t < NT2; t++) {
        asm volatile("cp.async.wait_group 0;" ::: "memory");
        __syncthreads();
        const uint32_t sK  = smbase + (t & 1) * 49152;
        const uint32_t sVp = smbase + ((t + 1) & 1) * 49152 + 32768;

        qk_tile(sK);
        phase2_pv(sVp);

        __syncthreads();
        if (t + 1 < NT2) {
            copy_tile(smbase + ((t + 1) & 1) * 49152, b, t + 1, tid);
            asm volatile("cp.async.commit_group;" ::: "memory");
        }
        phase1();
    }

    phase2_pv(smbase + ((NT2 - 1) & 1) * 49152 + 32768);
    __syncthreads();

    float* sm = (float*)smraw;
    const float i0 = 1.f / o[8][0], i1 = 1.f / o[8][2];
    const int r0 = w * 16 + g;
    #pragma unroll
    for (int nb = 0; nb < 8; nb++) {
        const int c0 = nb * 8 + 2 * tq;
        sm[c0 * 68 + r0]           = o[nb][0] * i0;
        sm[(c0 + 1) * 68 + r0]     = o[nb][1] * i0;
        sm[c0 * 68 + r0 + 8]       = o[nb][2] * i1;
        sm[(c0 + 1) * 68 + r0 + 8] = o[nb][3] * i1;
    }
    __syncthreads();
    #pragma unroll
    for (int k = 0; k < 8; k++) {
        int idx = tid + k * 128;
        int c = idx >> 4, i4 = (idx & 15) << 2;
        *(float4*)&out[((size_t)b * 64 + c) * 4096 + qblk * 64 + i4] =
            *(float4*)&sm[c * 68 + i4];
    }
}

// ---------------------------------------------------------------------------
// MERGED tensor-core QKV: one CTA per (128-token tile, batch) converts x ONCE,
// then loops m = q,k,v reloading only the small W-frag tile. Fast split2
// conversions throughout.
// ---------------------------------------------------------------------------
__global__ void __launch_bounds__(128, 1) qkv_tc(
    const float* __restrict__ x,
    const float* __restrict__ Wq, const float* __restrict__ bq,
    const float* __restrict__ Wk, const float* __restrict__ bk,
    const float* __restrict__ Wv, const float* __restrict__ bv)
{
    __shared__ uint4 WF[2][4][4][32];      // [hl][cs][jp][lane] : W frag tile
    __shared__ uint4 XF[2][2][4][4][32];   // [half][hl][cs][jp][lane] : x tile

    const int tid = threadIdx.x, lane = tid & 31, w = tid >> 5;
    const int g = lane >> 2, tq = lane & 3;
    const int n0 = blockIdx.x * 128, b = blockIdx.y;

    // --- convert x tile (64 ch x 128 tokens) ONCE into frag tile ---
    {
        uint32_t* xfu = (uint32_t*)XF;
        const int cp = tid >> 2, tqd = tid & 3;
        const int cs = cp >> 3;
        const float* x0p = x + ((size_t)(b * 64 + 2 * cp)) * 4096 + n0;
        const float* x1p = x0p + 4096;
        #pragma unroll
        for (int t4 = 0; t4 < 8; t4++) {
            int nn = tqd * 32 + t4 * 4;
            float4 v0 = *(const float4*)&x0p[nn];
            float4 v1 = *(const float4*)&x1p[nn];
            #pragma unroll
            for (int e = 0; e < 4; e++) {
                uint32_t hi, lo;
                split2((&v0.x)[e], (&v1.x)[e], hi, lo);
                int rr = nn + e, half = rr >> 6, r6 = rr & 63;
                int jp = (r6 >> 4) & 3, bsel = (r6 >> 3) & 1;
                int ln = (r6 & 7) * 4 + (cp & 3);
                int idx = bsel * 2 + ((cp >> 2) & 1);
                int off = half * 4096 + (cs * 4 + jp) * 128 + ln * 4 + idx;
                xfu[off] = hi;
                xfu[off + 2048] = lo;
            }
        }
    }

    #pragma unroll 1
    for (int m = 0; m < 3; m++) {
        const float* Wm = (m == 0) ? Wq : (m == 1) ? Wk : Wv;
        const float* bm = (m == 0) ? bq : (m == 1) ? bk : bv;

        __syncthreads();   // prior m's WF reads done (also orders x-convert)
        // --- convert W (64x64) into frag tile ---
        {
            uint32_t* wfu = (uint32_t*)WF;
            const int o = tid & 63, cg = tid >> 6;
            const int jp = (o >> 4) & 3, bsel = (o >> 3) & 1;
            #pragma unroll
            for (int f = 0; f < 8; f++) {
                int c4 = (cg * 8 + f) * 4;
                float4 wv = *(const float4*)&Wm[o * 64 + c4];
                #pragma unroll
                for (int h = 0; h < 2; h++) {
                    uint32_t hi, lo;
                    split2(h ? wv.z : wv.x, h ? wv.w : wv.y, hi, lo);
                    int kp = (c4 >> 1) + h;
                    int cs = kp >> 3, ln = (o & 7) * 4 + (kp & 3);
                    int idx = bsel * 2 + ((kp >> 2) & 1);
                    int off = (cs * 4 + jp) * 128 + ln * 4 + idx;
                    wfu[off] = hi;
                    wfu[off + 2048] = lo;
                }
            }
        }
        __syncthreads();

        if (m < 2) {
            // D = tokens(M) x out-channels(N); warp handles rowblocks 2w,2w+1
            #pragma unroll 1
            for (int rbi = 0; rbi < 2; rbi++) {
                const int rb = w * 2 + rbi;
                float acc[8][4];
                #pragma unroll
                for (int nb = 0; nb < 8; nb++)
                    #pragma unroll
                    for (int i = 0; i < 4; i++) acc[nb][i] = 0.f;

                #pragma unroll
                for (int cs = 0; cs < 4; cs++) {
                    uint4 Xh = XF[rb >> 2][0][cs][rb & 3][lane];
                    uint4 Xl = XF[rb >> 2][1][cs][rb & 3][lane];
                    uint32_t ah[4] = { Xh.x, Xh.z, Xh.y, Xh.w };
                    uint32_t al[4] = { Xl.x, Xl.z, Xl.y, Xl.w };
                    #pragma unroll
                    for (int jp = 0; jp < 4; jp++) {
                        uint4 Wh = WF[0][cs][jp][lane];
                        uint4 Wl = WF[1][cs][jp][lane];
                        mma16816(acc[2*jp],   ah, Wh.x, Wh.y);
                        mma16816(acc[2*jp],   al, Wh.x, Wh.y);
                        mma16816(acc[2*jp],   ah, Wl.x, Wl.y);
                        mma16816(acc[2*jp+1], ah, Wh.z, Wh.w);
                        mma16816(acc[2*jp+1], al, Wh.z, Wh.w);
                        mma16816(acc[2*jp+1], ah, Wl.z, Wl.w);
                    }
                }

                #pragma unroll
                for (int nb = 0; nb < 8; nb++) {
                    float bb0 = __ldg(&bm[nb * 8 + 2 * tq]);
                    float bb1 = __ldg(&bm[nb * 8 + 2 * tq + 1]);
                    acc[nb][0] += bb0; acc[nb][1] += bb1;
                    acc[nb][2] += bb0; acc[nb][3] += bb1;
                    if (m == 0) {
                        acc[nb][0] *= LOG2E; acc[nb][1] *= LOG2E;
                        acc[nb][2] *= LOG2E; acc[nb][3] *= LOG2E;
                    }
                }

                uint32_t uAh[8], uBh[8], uAl[8], uBl[8];
                #pragma unroll
                for (int nb = 0; nb < 8; nb++) {
                    split2(acc[nb][0], acc[nb][1], uAh[nb], uAl[nb]);
                    split2(acc[nb][2], acc[nb][3], uBh[nb], uBl[nb]);
                }

                const int rowblk = (n0 >> 4) + rb;
                if (m == 0) {
                    uint4* dst = g_qf + ((size_t)(b * 256 + rowblk)) * 256 + lane;
                    #pragma unroll
                    for (int cs = 0; cs < 4; cs++) {
                        dst[cs * 32] = make_uint4(uAh[2*cs], uBh[2*cs],
                                                  uAh[2*cs+1], uBh[2*cs+1]);
                        dst[128 + cs * 32] = make_uint4(uAl[2*cs], uBl[2*cs],
                                                        uAl[2*cs+1], uBl[2*cs+1]);
                    }
                } else {
                    const int jblk = rowblk >> 2, jp2 = rowblk & 3;
                    uint4* dst = g_kf + ((size_t)(b * 64 + jblk)) * 1024
                               + jp2 * 32 + lane;
                    #pragma unroll
                    for (int cs = 0; cs < 4; cs++) {
                        dst[cs * 128] = make_uint4(uAh[2*cs], uAh[2*cs+1],
                                                   uBh[2*cs], uBh[2*cs+1]);
                        dst[512 + cs * 128] = make_uint4(uAl[2*cs], uAl[2*cs+1],
                                                         uBl[2*cs], uBl[2*cs+1]);
                    }
                }
            }
        } else {
            // V: D = out-channels(M) x tokens(N); warp w owns channel blk 16w
            float acc[16][4];
            #pragma unroll
            for (int nb = 0; nb < 16; nb++)
                #pragma unroll
                for (int i = 0; i < 4; i++) acc[nb][i] = 0.f;

            #pragma unroll
            for (int cs = 0; cs < 4; cs++) {
                uint4 Ah4 = WF[0][cs][w][lane];
                uint4 Al4 = WF[1][cs][w][lane];
                uint32_t ah[4] = { Ah4.x, Ah4.z, Ah4.y, Ah4.w };
                uint32_t al[4] = { Al4.x, Al4.z, Al4.y, Al4.w };
                #pragma unroll
                for (int jp = 0; jp < 8; jp++) {
                    uint4 Xh = XF[jp >> 2][0][cs][jp & 3][lane];
                    uint4 Xl = XF[jp >> 2][1][cs][jp & 3][lane];
                    mma16816(acc[2*jp],   ah, Xh.x, Xh.y);
                    mma16816(acc[2*jp],   al, Xh.x, Xh.y);
                    mma16816(acc[2*jp],   ah, Xl.x, Xl.y);
                    mma16816(acc[2*jp+1], ah, Xh.z, Xh.w);
                    mma16816(acc[2*jp+1], al, Xh.z, Xh.w);
                    mma16816(acc[2*jp+1], ah, Xl.z, Xl.w);
                }
            }

            const float bb0 = __ldg(&bm[16 * w + g]);
            const float bb1 = __ldg(&bm[16 * w + g + 8]);
            uint32_t uA[16], uB[16];
            #pragma unroll
            for (int nb = 0; nb < 16; nb++) {
                uA[nb] = pkh(acc[nb][0] + bb0, acc[nb][1] + bb0);
                uB[nb] = pkh(acc[nb][2] + bb1, acc[nb][3] + bb1);
            }
            #pragma unroll
            for (int ks = 0; ks < 8; ks++) {
                const int jblk = (n0 >> 6) + (ks >> 2), ksl = ks & 3;
                g_vf[((size_t)(b * 64 + jblk)) * 512 + ksl * 128 + w * 32 + lane]
                    = make_uint4(uA[2*ks], uA[2*ks+1], uB[2*ks], uB[2*ks+1]);
            }
        }
    }
}

// ---------------------------------------------------------------------------
// Inputs (metadata order): x, t(unused), Wq, bq, Wk, bk, Wv, bv
// ---------------------------------------------------------------------------
extern "C" void kernel_launch(void* const* d_in, const int* in_sizes, int n_in,
                              void* d_out, int out_size) {
    const float* x  = (const float*)d_in[0];
    const float* Wq = (const float*)d_in[2];
    const float* bq = (const float*)d_in[3];
    const float* Wk = (const float*)d_in[4];
    const float* bk = (const float*)d_in[5];
    const float* Wv = (const float*)d_in[6];
    const float* bv = (const float*)d_in[7];
    float* out = (float*)d_out;

    cudaFuncSetAttribute(attn_tc, cudaFuncAttributeMaxDynamicSharedMemorySize,
                         98304);
    qkv_tc<<<dim3(32, B_), 128>>>(x, Wq, bq, Wk, bk, Wv, bv);
    attn_tc<<<B_ * 64, 128, 98304>>>(out);
}